// round 10
// baseline (speedup 1.0000x reference)
#include <cuda_runtime.h>
#include <cstdint>

// VQ on GB300 — SIMT f32x2: TPB 256 (4 warps/SMSP), CH=64 double-buffered
// (R2 control flow), acc[4][4] tile (no spills). Exact fp32 numerics.

#define NROWS  131072
#define CDIM   64
#define NE     1024
#define TPB    256
#define RPB    128                 // rows per block
#define NBLK   (NROWS/RPB)         // 1024
#define CH     64                  // codes per smem chunk
#define NCH    (NE/CH)             // 16

typedef unsigned long long ull;

__device__ ull    g_eTd[CDIM * NE];  // [k][c] -> {e,e}  (512KB)
__device__ ull    g_e2d[NE];         // {||e||^2, ||e||^2}
__device__ double g_loss_acc;

__device__ __forceinline__ ull pk2(float lo, float hi) {
    ull d; asm("mov.b64 %0, {%1, %2};" : "=l"(d) : "f"(lo), "f"(hi)); return d;
}
__device__ __forceinline__ void upk2(ull v, float& lo, float& hi) {
    asm("mov.b64 {%0, %1}, %2;" : "=f"(lo), "=f"(hi) : "l"(v));
}
__device__ __forceinline__ ull ffma2(ull a, ull b, ull c) {
    ull d; asm("fma.rn.f32x2 %0, %1, %2, %3;" : "=l"(d) : "l"(a), "l"(b), "l"(c)); return d;
}
__device__ __forceinline__ ull add2(ull a, ull b) {
    ull d; asm("add.rn.f32x2 %0, %1, %2;" : "=l"(d) : "l"(a), "l"(b)); return d;
}
__device__ __forceinline__ void cpa16(void* dst, const void* src) {
    unsigned sd = (unsigned)__cvta_generic_to_shared(dst);
    asm volatile("cp.async.cg.shared.global [%0], [%1], 16;" :: "r"(sd), "l"(src));
}
#define CPA_COMMIT() asm volatile("cp.async.commit_group;")
#define CPA_WAIT0()  asm volatile("cp.async.wait_group 0;" ::: "memory")
#define CPA_WAIT1()  asm volatile("cp.async.wait_group 1;" ::: "memory")

// Prologue 1: transpose + duplicate codebook into g_eTd; zero loss acc.
__global__ void vq_prep(const float* __restrict__ embs) {
    int idx = blockIdx.x * 256 + threadIdx.x;      // = c*64 + k (coalesced read)
    if (idx == 0) g_loss_acc = 0.0;
    float v = embs[idx];
    int c = idx >> 6, k = idx & 63;
    g_eTd[k * NE + c] = pk2(v, v);
}

// Prologue 2: per-code squared norms (duplicated).
__global__ void vq_prep2(const float* __restrict__ embs) {
    int c = blockIdx.x * 128 + threadIdx.x;
    const float4* p = (const float4*)(embs + (size_t)c * CDIM);
    float s = 0.f;
    #pragma unroll
    for (int q = 0; q < 16; q++) {
        float4 v = p[q];
        s += v.x * v.x + v.y * v.y + v.z * v.z + v.w * v.w;
    }
    g_e2d[c] = pk2(s, s);
}

// smem layout (ull units):
//  sED  [2][64][64] : 8192 ull  e chunks (dup), double-buffered; reused in epilogue
//  zT   [64][64]    : 4096 ull  zT[k][p] = {z[2p][k], z[2p+1][k]}
//  sznf [128] f     :   64 ull
//  sidx [128] i     :   64 ull
//  sred [8] f       :    8 ull
//  sE2  [1024]      : 1024 ull  all code norms (dup)
#define SMEM_ULL  (8192 + 4096 + 64 + 64 + 8 + 1024)
#define SMEM_B    (SMEM_ULL * 8)

__global__ __launch_bounds__(TPB, 2) void vq_main(
    const float* __restrict__ ze, const float* __restrict__ embs,
    float* __restrict__ out)
{
    extern __shared__ ull sm[];
    ull*   sED  = sm;                         // [2][4096]
    ull*   zT   = sm + 8192;                  // [64][64]
    float* zTf  = (float*)zT;                 // [64][128]
    float* sznf = (float*)(sm + 12288);       // [128]
    int*   sidx = (int*)(sm + 12352);         // [128]
    float* sred = (float*)(sm + 12416);       // [8]
    ull*   sE2  = sm + 12424;                 // [1024]

    const int tid = threadIdx.x;
    const int w   = tid >> 5;
    const int ln  = tid & 31;
    const int rg  = tid & 15;                 // row group (16) -> pairs rg*4..+3
    const int cg  = tid >> 4;                 // code group (16) -> codes cg*4..+3
    const size_t row0 = (size_t)blockIdx.x * RPB;

    // stage all code norms + chunk 0 (first cp.async group)
    #pragma unroll
    for (int i = 0; i < 2; i++) {
        int u = i * TPB + tid;                // 512 x 16B = 8KB
        cpa16(&sE2[u * 2], &g_e2d[u * 2]);
    }
    #pragma unroll
    for (int i = 0; i < 8; i++) {
        int u = i * TPB + tid;                // 2048 units: k = u>>5, c2 = u&31
        int k = u >> 5, c2 = u & 31;
        cpa16(&sED[k * 64 + c2 * 2], &g_eTd[k * NE + c2 * 2]);
    }
    CPA_COMMIT();

    // build z tile (transposed, pair-packed) + row norms
    {
        const int row = tid >> 1, h = tid & 1;       // h: k-half 32*h..32*h+31
        const float4* zr = (const float4*)(ze + (row0 + row) * CDIM + h * 32);
        float zn = 0.f;
        #pragma unroll
        for (int q = 0; q < 8; q++) {
            float4 v = zr[q];
            int k = h * 32 + q * 4;
            zTf[(k + 0) * 128 + row] = v.x;
            zTf[(k + 1) * 128 + row] = v.y;
            zTf[(k + 2) * 128 + row] = v.z;
            zTf[(k + 3) * 128 + row] = v.w;
            zn += v.x * v.x + v.y * v.y + v.z * v.z + v.w * v.w;
        }
        zn += __shfl_xor_sync(0xffffffffu, zn, 1);   // combine the two k-halves
        if (h == 0) sznf[row] = zn;
    }
    __syncthreads();

    ull znj[4];
    #pragma unroll
    for (int j = 0; j < 4; j++) znj[j] = ((const ull*)sznf)[rg * 4 + j];

    float best[8]; int bidx[8];
    #pragma unroll
    for (int i = 0; i < 8; i++) { best[i] = 3.4e38f; bidx[i] = 0; }

    const ull  M2 = pk2(-2.f, -2.f);
    const ull* zbase = zT + rg * 4;

    for (int ch = 0; ch < NCH; ch++) {
        const int b = ch & 1;
        if (ch + 1 < NCH) {
            const int nb = (ch + 1) & 1;
            #pragma unroll
            for (int i = 0; i < 8; i++) {
                int u = i * TPB + tid;
                int k = u >> 5, c2 = u & 31;
                cpa16(&sED[nb * 4096 + k * 64 + c2 * 2],
                      &g_eTd[k * NE + (ch + 1) * CH + c2 * 2]);
            }
            CPA_COMMIT();
            CPA_WAIT1();                       // chunk ch resident; ch+1 in flight
        } else {
            CPA_WAIT0();
        }
        __syncthreads();

        const ull* ebase = sED + b * 4096 + cg * 4;
        ull acc[4][4];
        #pragma unroll
        for (int j = 0; j < 4; j++)
            #pragma unroll
            for (int c = 0; c < 4; c++) acc[j][c] = 0ull;

        // 16 FFMA2 : 4 LDS.128 per k
        #pragma unroll 8
        for (int k = 0; k < CDIM; k++) {
            const ulonglong2* zk = (const ulonglong2*)(zbase + k * 64);
            const ulonglong2* ek = (const ulonglong2*)(ebase + k * 64);
            ulonglong2 za = zk[0], zb = zk[1];
            ulonglong2 e0 = ek[0], e1 = ek[1];
            ull zr_[4] = { za.x, za.y, zb.x, zb.y };
            ull er_[4] = { e0.x, e0.y, e1.x, e1.y };
            #pragma unroll
            for (int j = 0; j < 4; j++)
                #pragma unroll
                for (int c = 0; c < 4; c++)
                    acc[j][c] = ffma2(zr_[j], er_[c], acc[j][c]);
        }

        // dist = (||z||^2 + ||e||^2) - 2*dot ; strict < + ascending index
        #pragma unroll
        for (int c = 0; c < 4; c++) {
            int ci  = ch * CH + cg * 4 + c;
            ull e2d = sE2[ci];
            #pragma unroll
            for (int j = 0; j < 4; j++) {
                ull d2 = ffma2(acc[j][c], M2, add2(znj[j], e2d));
                float dlo, dhi; upk2(d2, dlo, dhi);
                if (dlo < best[j * 2])     { best[j * 2]     = dlo; bidx[j * 2]     = ci; }
                if (dhi < best[j * 2 + 1]) { best[j * 2 + 1] = dhi; bidx[j * 2 + 1] = ci; }
            }
        }
        __syncthreads();   // protect buffer b before it is reloaded at ch+2
    }

    // cross code-group reduction: 16 cgs per row; reuse sED
    float* resf = (float*)sED;                 // [16][128]
    int*   resi = (int*)(sED + 1024);          // [16][128]
    #pragma unroll
    for (int rl = 0; rl < 8; rl++) {
        int r = rg * 8 + rl;
        resf[cg * 128 + r] = best[rl];
        resi[cg * 128 + r] = bidx[rl];
    }
    __syncthreads();

    if (tid < RPB) {
        float bv = resf[tid]; int bi = resi[tid];
        #pragma unroll
        for (int g = 1; g < 16; g++) {
            float v = resf[g * 128 + tid];
            int  ii = resi[g * 128 + tid];
            if (v < bv || (v == bv && ii < bi)) { bv = v; bi = ii; }
        }
        sidx[tid] = bi;
    }
    __syncthreads();

    // warp-cooperative coalesced output: warp w -> rows w*16..+15
    float ls = 0.f;
    #pragma unroll
    for (int r16 = 0; r16 < 16; r16++) {
        const int row = w * 16 + r16;
        const int code = sidx[row];
        float2 e = ((const float2*)(embs + (size_t)code * CDIM))[ln];
        float2 z = ((const float2*)(ze + (row0 + row) * CDIM))[ln];
        ((float2*)(out + (row0 + row) * CDIM))[ln] = e;
        float d0 = e.x - z.x, d1 = e.y - z.y;
        ls += d0 * d0 + d1 * d1;
    }
    #pragma unroll
    for (int off = 16; off > 0; off >>= 1)
        ls += __shfl_down_sync(0xffffffffu, ls, off);
    if (ln == 0) sred[w] = ls;
    __syncthreads();
    if (tid == 0) {
        float s = 0.f;
        #pragma unroll
        for (int i = 0; i < 8; i++) s += sred[i];
        atomicAdd(&g_loss_acc, (double)s);
    }
}

__global__ void vq_fin(float* loss_out) {
    *loss_out = (float)(1.25 * g_loss_acc / (double)((long long)NROWS * CDIM));
}

extern "C" void kernel_launch(void* const* d_in, const int* in_sizes, int n_in,
                              void* d_out, int out_size) {
    const float* ze   = (const float*)d_in[0];
    const float* embs = (const float*)d_in[1];
    float* out = (float*)d_out;

    cudaFuncSetAttribute(vq_main, cudaFuncAttributeMaxDynamicSharedMemorySize, SMEM_B);

    vq_prep<<<NE * CDIM / 256, 256>>>(embs);
    vq_prep2<<<NE / 128, 128>>>(embs);
    vq_main<<<NBLK, TPB, SMEM_B>>>(ze, embs, out);
    if (out_size > NROWS * CDIM)
        vq_fin<<<1, 1>>>(out + (out_size - 1));
}

// round 11
// speedup vs baseline: 1.2883x; 1.2883x over previous
#include <cuda_runtime.h>
#include <cstdint>

// VQ on GB300 — SIMT f32x2, R11: TPB 512, 1 block/SM (16 warps = 4/SMSP),
// CH=128 double-buffered (copy fully hidden), grid 1024 -> 7 waves (1.2% tail).
// Thread tile: 2 row-pairs x 8 codes; e-loads warp-broadcast. Exact fp32.

#define NROWS  131072
#define CDIM   64
#define NE     1024
#define TPB    512
#define RPB    128                 // rows per block
#define NBLK   (NROWS/RPB)         // 1024
#define CH     128                 // codes per smem chunk
#define NCH    (NE/CH)             // 8

typedef unsigned long long ull;

__device__ ull    g_eTd[CDIM * NE];  // [k][c] -> {e,e}  (512KB)
__device__ ull    g_e2d[NE];         // {||e||^2, ||e||^2}
__device__ double g_loss_acc;

__device__ __forceinline__ ull pk2(float lo, float hi) {
    ull d; asm("mov.b64 %0, {%1, %2};" : "=l"(d) : "f"(lo), "f"(hi)); return d;
}
__device__ __forceinline__ void upk2(ull v, float& lo, float& hi) {
    asm("mov.b64 {%0, %1}, %2;" : "=f"(lo), "=f"(hi) : "l"(v));
}
__device__ __forceinline__ ull ffma2(ull a, ull b, ull c) {
    ull d; asm("fma.rn.f32x2 %0, %1, %2, %3;" : "=l"(d) : "l"(a), "l"(b), "l"(c)); return d;
}
__device__ __forceinline__ ull add2(ull a, ull b) {
    ull d; asm("add.rn.f32x2 %0, %1, %2;" : "=l"(d) : "l"(a), "l"(b)); return d;
}
__device__ __forceinline__ void cpa16(void* dst, const void* src) {
    unsigned sd = (unsigned)__cvta_generic_to_shared(dst);
    asm volatile("cp.async.cg.shared.global [%0], [%1], 16;" :: "r"(sd), "l"(src));
}
#define CPA_COMMIT() asm volatile("cp.async.commit_group;")
#define CPA_WAIT0()  asm volatile("cp.async.wait_group 0;" ::: "memory")
#define CPA_WAIT1()  asm volatile("cp.async.wait_group 1;" ::: "memory")

// Prologue 1: transpose + duplicate codebook into g_eTd; zero loss acc.
__global__ void vq_prep(const float* __restrict__ embs) {
    int idx = blockIdx.x * 256 + threadIdx.x;      // = c*64 + k (coalesced read)
    if (idx == 0) g_loss_acc = 0.0;
    float v = embs[idx];
    int c = idx >> 6, k = idx & 63;
    g_eTd[k * NE + c] = pk2(v, v);
}

// Prologue 2: per-code squared norms (duplicated).
__global__ void vq_prep2(const float* __restrict__ embs) {
    int c = blockIdx.x * 128 + threadIdx.x;
    const float4* p = (const float4*)(embs + (size_t)c * CDIM);
    float s = 0.f;
    #pragma unroll
    for (int q = 0; q < 16; q++) {
        float4 v = p[q];
        s += v.x * v.x + v.y * v.y + v.z * v.z + v.w * v.w;
    }
    g_e2d[c] = pk2(s, s);
}

// smem layout (ull units):
//  sED  [2][64][128] : 16384 ull  e chunks (dup), double-buffered; reused in epilogue
//  zT   [64][64]     :  4096 ull  zT[k][p] = {z[2p][k], z[2p+1][k]}
//  sE2  [1024]       :  1024 ull  all code norms (dup)
//  sznf [128] f      :    64 ull
//  sidx [128] i      :    64 ull
//  sred [16] f       :     8 ull
#define SMEM_ULL  (16384 + 4096 + 1024 + 64 + 64 + 8)
#define SMEM_B    (SMEM_ULL * 8)

__global__ __launch_bounds__(TPB) void vq_main(
    const float* __restrict__ ze, const float* __restrict__ embs,
    float* __restrict__ out)
{
    extern __shared__ ull sm[];
    ull*   sED  = sm;                         // [2][8192]
    ull*   zT   = sm + 16384;                 // [64][64]
    float* zTf  = (float*)zT;                 // [64][128]
    ull*   sE2  = sm + 20480;                 // [1024]
    float* sznf = (float*)(sm + 21504);       // [128]
    int*   sidx = (int*)(sm + 21568);         // [128]
    float* sred = (float*)(sm + 21632);       // [16]

    const int tid = threadIdx.x;
    const int w   = tid >> 5;                 // warp = code group (16) -> codes w*8..+7
    const int ln  = tid & 31;                 // lane = row group (32) -> pairs ln*2..+1
    const size_t row0 = (size_t)blockIdx.x * RPB;

    // stage sE2 + chunk 0 (group 0), chunk 1 (group 1)
    cpa16(&sE2[tid * 2], &g_e2d[tid * 2]);
    #pragma unroll
    for (int i = 0; i < 8; i++) {
        int u = i * TPB + tid;                // 4096 x 16B: k = u>>6, c2 = u&63
        int k = u >> 6, c2 = u & 63;
        cpa16(&sED[k * 128 + c2 * 2], &g_eTd[k * NE + c2 * 2]);
    }
    CPA_COMMIT();
    #pragma unroll
    for (int i = 0; i < 8; i++) {
        int u = i * TPB + tid;
        int k = u >> 6, c2 = u & 63;
        cpa16(&sED[8192 + k * 128 + c2 * 2], &g_eTd[k * NE + CH + c2 * 2]);
    }
    CPA_COMMIT();

    // build z tile (transposed, pair-packed) + row norms
    {
        const int row = tid >> 2, q4 = tid & 3;       // q4: 16-k quarter
        const float4* zr = (const float4*)(ze + (row0 + row) * CDIM + q4 * 16);
        float zn = 0.f;
        #pragma unroll
        for (int i = 0; i < 4; i++) {
            float4 v = zr[i];
            int k = q4 * 16 + i * 4;
            zTf[(k + 0) * 128 + row] = v.x;
            zTf[(k + 1) * 128 + row] = v.y;
            zTf[(k + 2) * 128 + row] = v.z;
            zTf[(k + 3) * 128 + row] = v.w;
            zn += v.x * v.x + v.y * v.y + v.z * v.z + v.w * v.w;
        }
        zn += __shfl_xor_sync(0xffffffffu, zn, 1);
        zn += __shfl_xor_sync(0xffffffffu, zn, 2);
        if (q4 == 0) sznf[row] = zn;
    }
    __syncthreads();

    ull znj[2];
    #pragma unroll
    for (int j = 0; j < 2; j++) znj[j] = ((const ull*)sznf)[ln * 2 + j];

    float best[4]; int bidx[4];
    #pragma unroll
    for (int i = 0; i < 4; i++) { best[i] = 3.4e38f; bidx[i] = 0; }

    const ull M2 = pk2(-2.f, -2.f);

    for (int ch = 0; ch < NCH; ch++) {
        const int b = ch & 1;
        if (ch < NCH - 1) CPA_WAIT1(); else CPA_WAIT0();
        __syncthreads();                       // chunk ch resident for all threads

        const ull* ebase = sED + b * 8192 + w * 8;
        const ull* zbase = zT + ln * 2;
        ull acc[2][8];
        #pragma unroll
        for (int j = 0; j < 2; j++)
            #pragma unroll
            for (int c = 0; c < 8; c++) acc[j][c] = 0ull;

        // 16 FFMA2 : 5 LDS.128 per k; e loads whole-warp broadcast
        #pragma unroll 8
        for (int k = 0; k < CDIM; k++) {
            const ulonglong2* zk = (const ulonglong2*)(zbase + k * 64);
            const ulonglong2* ek = (const ulonglong2*)(ebase + k * 128);
            ulonglong2 za = zk[0];
            ulonglong2 e0 = ek[0], e1 = ek[1], e2v = ek[2], e3 = ek[3];
            ull zr_[2] = { za.x, za.y };
            ull er_[8] = { e0.x, e0.y, e1.x, e1.y, e2v.x, e2v.y, e3.x, e3.y };
            #pragma unroll
            for (int j = 0; j < 2; j++)
                #pragma unroll
                for (int c = 0; c < 8; c++)
                    acc[j][c] = ffma2(zr_[j], er_[c], acc[j][c]);
        }
        __syncthreads();                       // all warps done reading buffer b

        if (ch + 2 < NCH) {                    // refill buffer b with chunk ch+2;
            #pragma unroll                     // overlaps the finalize below + next chunk
            for (int i = 0; i < 8; i++) {
                int u = i * TPB + tid;
                int k = u >> 6, c2 = u & 63;
                cpa16(&sED[b * 8192 + k * 128 + c2 * 2],
                      &g_eTd[k * NE + (ch + 2) * CH + c2 * 2]);
            }
            CPA_COMMIT();
        }

        // dist = (||z||^2 + ||e||^2) - 2*dot ; strict < + ascending index
        #pragma unroll
        for (int c = 0; c < 8; c++) {
            int ci  = ch * CH + w * 8 + c;
            ull e2d = sE2[ci];
            #pragma unroll
            for (int j = 0; j < 2; j++) {
                ull d2 = ffma2(acc[j][c], M2, add2(znj[j], e2d));
                float dlo, dhi; upk2(d2, dlo, dhi);
                if (dlo < best[j * 2])     { best[j * 2]     = dlo; bidx[j * 2]     = ci; }
                if (dhi < best[j * 2 + 1]) { best[j * 2 + 1] = dhi; bidx[j * 2 + 1] = ci; }
            }
        }
    }

    // cross code-group reduction: thread (ln,w) owns rows ln*4..+3; reuse sED
    float* resf = (float*)sED;                 // [16][128]
    int*   resi = (int*)(sED + 1024);          // [16][128]
    __syncthreads();                           // sED safe to reuse (all compute done)
    #pragma unroll
    for (int rl = 0; rl < 4; rl++) {
        int r = ln * 4 + rl;
        resf[w * 128 + r] = best[rl];
        resi[w * 128 + r] = bidx[rl];
    }
    __syncthreads();

    if (tid < RPB) {
        float bv = resf[tid]; int bi = resi[tid];
        #pragma unroll
        for (int g = 1; g < 16; g++) {
            float v = resf[g * 128 + tid];
            int  ii = resi[g * 128 + tid];
            if (v < bv || (v == bv && ii < bi)) { bv = v; bi = ii; }
        }
        sidx[tid] = bi;
    }
    __syncthreads();

    // warp-cooperative coalesced output: warp w -> rows w*8..+7
    float ls = 0.f;
    #pragma unroll
    for (int r8 = 0; r8 < 8; r8++) {
        const int row = w * 8 + r8;
        const int code = sidx[row];
        float2 e = ((const float2*)(embs + (size_t)code * CDIM))[ln];
        float2 z = ((const float2*)(ze + (row0 + row) * CDIM))[ln];
        ((float2*)(out + (row0 + row) * CDIM))[ln] = e;
        float d0 = e.x - z.x, d1 = e.y - z.y;
        ls += d0 * d0 + d1 * d1;
    }
    #pragma unroll
    for (int off = 16; off > 0; off >>= 1)
        ls += __shfl_down_sync(0xffffffffu, ls, off);
    if (ln == 0) sred[w] = ls;
    __syncthreads();
    if (tid == 0) {
        float s = 0.f;
        #pragma unroll
        for (int i = 0; i < 16; i++) s += sred[i];
        atomicAdd(&g_loss_acc, (double)s);
    }
}

__global__ void vq_fin(float* loss_out) {
    *loss_out = (float)(1.25 * g_loss_acc / (double)((long long)NROWS * CDIM));
}

extern "C" void kernel_launch(void* const* d_in, const int* in_sizes, int n_in,
                              void* d_out, int out_size) {
    const float* ze   = (const float*)d_in[0];
    const float* embs = (const float*)d_in[1];
    float* out = (float*)d_out;

    cudaFuncSetAttribute(vq_main, cudaFuncAttributeMaxDynamicSharedMemorySize, SMEM_B);

    vq_prep<<<NE * CDIM / 256, 256>>>(embs);
    vq_prep2<<<NE / 128, 128>>>(embs);
    vq_main<<<NBLK, TPB, SMEM_B>>>(ze, embs, out);
    if (out_size > NROWS * CDIM)
        vq_fin<<<1, 1>>>(out + (out_size - 1));
}

// round 12
// speedup vs baseline: 1.7766x; 1.3791x over previous
#include <cuda_runtime.h>
#include <cstdint>

// VQ on GB300 — SIMT f32x2, R12: R9 tile (acc[4][8], 32 FFMA2/k) + de-dup
// codebook in smem ({e,e} packed in-register) -> CH=128 double-buffered at
// 2 blocks/SM. Dummy first launch shifts vq_main to ncu's capture slot (#4).

#define NROWS  131072
#define CDIM   64
#define NE     1024
#define TPB    256
#define RPB    128                 // rows per block
#define NBLK   (NROWS/RPB)         // 1024
#define CH     128                 // codes per smem chunk
#define NCH    (NE/CH)             // 8

typedef unsigned long long ull;

__device__ float  g_eT[CDIM * NE];   // [k][c] transposed codebook (256KB)
__device__ float  g_e2[NE];
__device__ double g_loss_acc;

__device__ __forceinline__ ull pk2(float lo, float hi) {
    ull d; asm("mov.b64 %0, {%1, %2};" : "=l"(d) : "f"(lo), "f"(hi)); return d;
}
__device__ __forceinline__ void upk2(ull v, float& lo, float& hi) {
    asm("mov.b64 {%0, %1}, %2;" : "=f"(lo), "=f"(hi) : "l"(v));
}
__device__ __forceinline__ ull ffma2(ull a, ull b, ull c) {
    ull d; asm("fma.rn.f32x2 %0, %1, %2, %3;" : "=l"(d) : "l"(a), "l"(b), "l"(c)); return d;
}
__device__ __forceinline__ ull add2(ull a, ull b) {
    ull d; asm("add.rn.f32x2 %0, %1, %2;" : "=l"(d) : "l"(a), "l"(b)); return d;
}
__device__ __forceinline__ void cpa16(void* dst, const void* src) {
    unsigned sd = (unsigned)__cvta_generic_to_shared(dst);
    asm volatile("cp.async.cg.shared.global [%0], [%1], 16;" :: "r"(sd), "l"(src));
}
#define CPA_COMMIT() asm volatile("cp.async.commit_group;")
#define CPA_WAIT0()  asm volatile("cp.async.wait_group 0;" ::: "memory")
#define CPA_WAIT1()  asm volatile("cp.async.wait_group 1;" ::: "memory")

// Launch #1: dummy (zeroes the loss accumulator) — shifts vq_main to launch #4
// where the fixed ncu capture window lands.
__global__ void vq_zero() { g_loss_acc = 0.0; }

// Launch #2: transpose codebook (plain floats).
__global__ void vq_prep(const float* __restrict__ embs) {
    int idx = blockIdx.x * 256 + threadIdx.x;      // = c*64 + k (coalesced read)
    float v = embs[idx];
    int c = idx >> 6, k = idx & 63;
    g_eT[k * NE + c] = v;
}

// Launch #3: per-code squared norms.
__global__ void vq_prep2(const float* __restrict__ embs) {
    int c = blockIdx.x * 128 + threadIdx.x;
    const float4* p = (const float4*)(embs + (size_t)c * CDIM);
    float s = 0.f;
    #pragma unroll
    for (int q = 0; q < 16; q++) {
        float4 v = p[q];
        s += v.x * v.x + v.y * v.y + v.z * v.z + v.w * v.w;
    }
    g_e2[c] = s;
}

// smem layout:
//  sEDf [2][64][128] f : 64KB  e chunks (plain f32), double-buffered
//  zT   [64][64] ull   : 32KB  zT[k][p] = {z[2p][k], z[2p+1][k]}
//  sE2f [1024] f       :  4KB
//  sznf [128] f, sidx [128] i, sred [8] f : ~1KB
#define SMEM_B  (65536 + 32768 + 4096 + 1088)

__global__ __launch_bounds__(TPB, 2) void vq_main(
    const float* __restrict__ ze, const float* __restrict__ embs,
    float* __restrict__ out)
{
    extern __shared__ unsigned char smraw[];
    float* sEDf = (float*)smraw;                      // [2][8192]
    ull*   zT   = (ull*)(smraw + 65536);              // [64][64]
    float* zTf  = (float*)zT;                         // [64][128]
    float* sE2f = (float*)(smraw + 65536 + 32768);    // [1024]
    float* sznf = sE2f + 1024;                        // [128]
    int*   sidx = (int*)(sznf + 128);                 // [128]
    float* sred = (float*)(sidx + 128);               // [8]

    const int tid = threadIdx.x;
    const int w   = tid >> 5;
    const int ln  = tid & 31;
    const int rg  = tid & 15;                 // row group (16) -> pairs rg*4..+3
    const int cg  = tid >> 4;                 // code group (16) -> codes cg*8..+7
    const size_t row0 = (size_t)blockIdx.x * RPB;

    // group A: sE2 + chunk0 ; group B: chunk1
    cpa16(&sE2f[tid * 4], &g_e2[tid * 4]);
    #pragma unroll
    for (int i = 0; i < 8; i++) {
        int u = i * TPB + tid;                // 2048 x 16B; k = u>>5, c4 = u&31
        int k = u >> 5, c4 = u & 31;
        cpa16(&sEDf[k * 128 + c4 * 4], &g_eT[k * NE + c4 * 4]);
    }
    CPA_COMMIT();
    #pragma unroll
    for (int i = 0; i < 8; i++) {
        int u = i * TPB + tid;
        int k = u >> 5, c4 = u & 31;
        cpa16(&sEDf[8192 + k * 128 + c4 * 4], &g_eT[k * NE + CH + c4 * 4]);
    }
    CPA_COMMIT();

    // build z tile (transposed, pair-packed) + row norms
    {
        const int row = tid >> 1, h = tid & 1;       // h: k-half 32*h..32*h+31
        const float4* zr = (const float4*)(ze + (row0 + row) * CDIM + h * 32);
        float zn = 0.f;
        #pragma unroll
        for (int q = 0; q < 8; q++) {
            float4 v = zr[q];
            int k = h * 32 + q * 4;
            zTf[(k + 0) * 128 + row] = v.x;
            zTf[(k + 1) * 128 + row] = v.y;
            zTf[(k + 2) * 128 + row] = v.z;
            zTf[(k + 3) * 128 + row] = v.w;
            zn += v.x * v.x + v.y * v.y + v.z * v.z + v.w * v.w;
        }
        zn += __shfl_xor_sync(0xffffffffu, zn, 1);   // combine the two k-halves
        if (h == 0) sznf[row] = zn;
    }
    __syncthreads();

    ull znj[4];
    #pragma unroll
    for (int j = 0; j < 4; j++) znj[j] = ((const ull*)sznf)[rg * 4 + j];

    float best[8]; int bidx[8];
    #pragma unroll
    for (int i = 0; i < 8; i++) { best[i] = 3.4e38f; bidx[i] = 0; }

    const ull  M2 = pk2(-2.f, -2.f);
    const ull* zbase = zT + rg * 4;

    for (int ch = 0; ch < NCH; ch++) {
        const int b = ch & 1;
        if (ch < NCH - 1) CPA_WAIT1(); else CPA_WAIT0();
        __syncthreads();                       // chunk ch resident for all threads

        const float* ebase = sEDf + b * 8192 + cg * 8;
        ull acc[4][8];
        #pragma unroll
        for (int j = 0; j < 4; j++)
            #pragma unroll
            for (int c = 0; c < 8; c++) acc[j][c] = 0ull;

        // per k: 2 z-LDS.128 + 2 e-LDS.128 + 8 packs + 32 FFMA2
        #pragma unroll 8
        for (int k = 0; k < CDIM; k++) {
            const ulonglong2* zk = (const ulonglong2*)(zbase + k * 64);
            const float4*     ek = (const float4*)(ebase + k * 128);
            ulonglong2 za = zk[0], zb = zk[1];
            float4 ea = ek[0], eb = ek[1];
            ull zr_[4] = { za.x, za.y, zb.x, zb.y };
            ull er_[8] = { pk2(ea.x, ea.x), pk2(ea.y, ea.y),
                           pk2(ea.z, ea.z), pk2(ea.w, ea.w),
                           pk2(eb.x, eb.x), pk2(eb.y, eb.y),
                           pk2(eb.z, eb.z), pk2(eb.w, eb.w) };
            #pragma unroll
            for (int j = 0; j < 4; j++)
                #pragma unroll
                for (int c = 0; c < 8; c++)
                    acc[j][c] = ffma2(zr_[j], er_[c], acc[j][c]);
        }
        __syncthreads();                       // all threads done with buffer b

        if (ch + 2 < NCH) {                    // refill buffer b with chunk ch+2
            #pragma unroll
            for (int i = 0; i < 8; i++) {
                int u = i * TPB + tid;
                int k = u >> 5, c4 = u & 31;
                cpa16(&sEDf[b * 8192 + k * 128 + c4 * 4],
                      &g_eT[k * NE + (ch + 2) * CH + c4 * 4]);
            }
            CPA_COMMIT();
        }

        // dist = (||z||^2 + ||e||^2) - 2*dot ; strict < + ascending index
        #pragma unroll
        for (int c = 0; c < 8; c++) {
            int ci   = ch * CH + cg * 8 + c;
            float e2 = sE2f[ci];
            ull  e2d = pk2(e2, e2);
            #pragma unroll
            for (int j = 0; j < 4; j++) {
                ull d2 = ffma2(acc[j][c], M2, add2(znj[j], e2d));
                float dlo, dhi; upk2(d2, dlo, dhi);
                if (dlo < best[j * 2])     { best[j * 2]     = dlo; bidx[j * 2]     = ci; }
                if (dhi < best[j * 2 + 1]) { best[j * 2 + 1] = dhi; bidx[j * 2 + 1] = ci; }
            }
        }
    }

    // cross code-group reduction: 16 cgs per row; reuse sEDf
    float* resf = (float*)sEDf;                // [16][128]
    int*   resi = (int*)(sEDf + 2048);         // [16][128]
    __syncthreads();                           // compute done; sEDf reusable
    #pragma unroll
    for (int rl = 0; rl < 8; rl++) {
        int r = rg * 8 + rl;
        resf[cg * 128 + r] = best[rl];
        resi[cg * 128 + r] = bidx[rl];
    }
    __syncthreads();

    if (tid < RPB) {
        float bv = resf[tid]; int bi = resi[tid];
        #pragma unroll
        for (int g = 1; g < 16; g++) {
            float v = resf[g * 128 + tid];
            int  ii = resi[g * 128 + tid];
            if (v < bv || (v == bv && ii < bi)) { bv = v; bi = ii; }
        }
        sidx[tid] = bi;
    }
    __syncthreads();

    // warp-cooperative coalesced output: warp w -> rows w*16..+15
    float ls = 0.f;
    #pragma unroll
    for (int r16 = 0; r16 < 16; r16++) {
        const int row = w * 16 + r16;
        const int code = sidx[row];
        float2 e = ((const float2*)(embs + (size_t)code * CDIM))[ln];
        float2 z = ((const float2*)(ze + (row0 + row) * CDIM))[ln];
        ((float2*)(out + (row0 + row) * CDIM))[ln] = e;
        float d0 = e.x - z.x, d1 = e.y - z.y;
        ls += d0 * d0 + d1 * d1;
    }
    #pragma unroll
    for (int off = 16; off > 0; off >>= 1)
        ls += __shfl_down_sync(0xffffffffu, ls, off);
    if (ln == 0) sred[w] = ls;
    __syncthreads();
    if (tid == 0) {
        float s = 0.f;
        #pragma unroll
        for (int i = 0; i < 8; i++) s += sred[i];
        atomicAdd(&g_loss_acc, (double)s);
    }
}

__global__ void vq_fin(float* loss_out) {
    *loss_out = (float)(1.25 * g_loss_acc / (double)((long long)NROWS * CDIM));
}

extern "C" void kernel_launch(void* const* d_in, const int* in_sizes, int n_in,
                              void* d_out, int out_size) {
    const float* ze   = (const float*)d_in[0];
    const float* embs = (const float*)d_in[1];
    float* out = (float*)d_out;

    cudaFuncSetAttribute(vq_main, cudaFuncAttributeMaxDynamicSharedMemorySize, SMEM_B);

    vq_zero<<<1, 1>>>();                       // launch #1 (profiler shim + init)
    vq_prep<<<NE * CDIM / 256, 256>>>(embs);   // launch #2
    vq_prep2<<<NE / 128, 128>>>(embs);         // launch #3
    vq_main<<<NBLK, TPB, SMEM_B>>>(ze, embs, out);  // launch #4 <- ncu capture
    if (out_size > NROWS * CDIM)
        vq_fin<<<1, 1>>>(out + (out_size - 1));
}

// round 13
// speedup vs baseline: 1.9277x; 1.0850x over previous
#include <cuda_runtime.h>
#include <cstdint>

// VQ on GB300 — SIMT f32x2, R13: R12 + bank-conflict-free z-tile layout.
// z pair p=rg*4+j stored at ull column j*16+rg -> hot-loop z-loads are 4x
// LDS.64 at 8B lane stride (banks 0,2,..,30; conflict-free) instead of
// 2x LDS.128 at 32B stride (4-way conflict, the R12 L1=84.6% culprit).

#define NROWS  131072
#define CDIM   64
#define NE     1024
#define TPB    256
#define RPB    128                 // rows per block
#define NBLK   (NROWS/RPB)         // 1024
#define CH     128                 // codes per smem chunk
#define NCH    (NE/CH)             // 8

typedef unsigned long long ull;

__device__ float  g_eT[CDIM * NE];   // [k][c] transposed codebook (256KB)
__device__ float  g_e2[NE];
__device__ double g_loss_acc;

__device__ __forceinline__ ull pk2(float lo, float hi) {
    ull d; asm("mov.b64 %0, {%1, %2};" : "=l"(d) : "f"(lo), "f"(hi)); return d;
}
__device__ __forceinline__ void upk2(ull v, float& lo, float& hi) {
    asm("mov.b64 {%0, %1}, %2;" : "=f"(lo), "=f"(hi) : "l"(v));
}
__device__ __forceinline__ ull ffma2(ull a, ull b, ull c) {
    ull d; asm("fma.rn.f32x2 %0, %1, %2, %3;" : "=l"(d) : "l"(a), "l"(b), "l"(c)); return d;
}
__device__ __forceinline__ ull add2(ull a, ull b) {
    ull d; asm("add.rn.f32x2 %0, %1, %2;" : "=l"(d) : "l"(a), "l"(b)); return d;
}
__device__ __forceinline__ void cpa16(void* dst, const void* src) {
    unsigned sd = (unsigned)__cvta_generic_to_shared(dst);
    asm volatile("cp.async.cg.shared.global [%0], [%1], 16;" :: "r"(sd), "l"(src));
}
#define CPA_COMMIT() asm volatile("cp.async.commit_group;")
#define CPA_WAIT0()  asm volatile("cp.async.wait_group 0;" ::: "memory")
#define CPA_WAIT1()  asm volatile("cp.async.wait_group 1;" ::: "memory")

// Launch #1: dummy (zeroes loss acc) — keeps vq_main at ncu capture slot #4.
__global__ void vq_zero() { g_loss_acc = 0.0; }

// Launch #2: transpose codebook (plain floats).
__global__ void vq_prep(const float* __restrict__ embs) {
    int idx = blockIdx.x * 256 + threadIdx.x;      // = c*64 + k (coalesced read)
    float v = embs[idx];
    int c = idx >> 6, k = idx & 63;
    g_eT[k * NE + c] = v;
}

// Launch #3: per-code squared norms.
__global__ void vq_prep2(const float* __restrict__ embs) {
    int c = blockIdx.x * 128 + threadIdx.x;
    const float4* p = (const float4*)(embs + (size_t)c * CDIM);
    float s = 0.f;
    #pragma unroll
    for (int q = 0; q < 16; q++) {
        float4 v = p[q];
        s += v.x * v.x + v.y * v.y + v.z * v.z + v.w * v.w;
    }
    g_e2[c] = s;
}

// smem layout:
//  sEDf [2][64][128] f : 64KB  e chunks (plain f32), double-buffered
//  zT   [64][64] ull   : 32KB  interleaved: pair p at column (p&3)*16 + (p>>2)
//  sE2f [1024] f       :  4KB
//  sznf [128] f, sidx [128] i, sred [8] f : ~1KB
#define SMEM_B  (65536 + 32768 + 4096 + 1088)

__global__ __launch_bounds__(TPB, 2) void vq_main(
    const float* __restrict__ ze, const float* __restrict__ embs,
    float* __restrict__ out)
{
    extern __shared__ unsigned char smraw[];
    float* sEDf = (float*)smraw;                      // [2][8192]
    ull*   zT   = (ull*)(smraw + 65536);              // [64][64]
    float* zTf  = (float*)zT;                         // [64][128]
    float* sE2f = (float*)(smraw + 65536 + 32768);    // [1024]
    float* sznf = sE2f + 1024;                        // [128]
    int*   sidx = (int*)(sznf + 128);                 // [128]
    float* sred = (float*)(sidx + 128);               // [8]

    const int tid = threadIdx.x;
    const int w   = tid >> 5;
    const int ln  = tid & 31;
    const int rg  = tid & 15;                 // row group (16) -> pairs rg*4..+3
    const int cg  = tid >> 4;                 // code group (16) -> codes cg*8..+7
    const size_t row0 = (size_t)blockIdx.x * RPB;

    // group A: sE2 + chunk0 ; group B: chunk1
    cpa16(&sE2f[tid * 4], &g_e2[tid * 4]);
    #pragma unroll
    for (int i = 0; i < 8; i++) {
        int u = i * TPB + tid;                // 2048 x 16B; k = u>>5, c4 = u&31
        int k = u >> 5, c4 = u & 31;
        cpa16(&sEDf[k * 128 + c4 * 4], &g_eT[k * NE + c4 * 4]);
    }
    CPA_COMMIT();
    #pragma unroll
    for (int i = 0; i < 8; i++) {
        int u = i * TPB + tid;
        int k = u >> 5, c4 = u & 31;
        cpa16(&sEDf[8192 + k * 128 + c4 * 4], &g_eT[k * NE + CH + c4 * 4]);
    }
    CPA_COMMIT();

    // build z tile (transposed, pair-packed, j-major interleaved) + row norms
    // row r -> pair p = r>>1, half h = r&1; pair p lives at ull column
    // (p&3)*16 + (p>>2)  => float index col*2 + h
    {
        const int row = tid >> 1, h = tid & 1;       // h: k-half 32*h..32*h+31
        const int p   = row >> 1;
        const int fi  = (((p & 3) * 16 + (p >> 2)) << 1) + (row & 1);
        const float4* zr = (const float4*)(ze + (row0 + row) * CDIM + h * 32);
        float zn = 0.f;
        #pragma unroll
        for (int q = 0; q < 8; q++) {
            float4 v = zr[q];
            int k = h * 32 + q * 4;
            zTf[(k + 0) * 128 + fi] = v.x;
            zTf[(k + 1) * 128 + fi] = v.y;
            zTf[(k + 2) * 128 + fi] = v.z;
            zTf[(k + 3) * 128 + fi] = v.w;
            zn += v.x * v.x + v.y * v.y + v.z * v.z + v.w * v.w;
        }
        zn += __shfl_xor_sync(0xffffffffu, zn, 1);   // combine the two k-halves
        if (h == 0) sznf[row] = zn;
    }
    __syncthreads();

    ull znj[4];
    #pragma unroll
    for (int j = 0; j < 4; j++) znj[j] = ((const ull*)sznf)[rg * 4 + j];

    float best[8]; int bidx[8];
    #pragma unroll
    for (int i = 0; i < 8; i++) { best[i] = 3.4e38f; bidx[i] = 0; }

    const ull M2 = pk2(-2.f, -2.f);

    for (int ch = 0; ch < NCH; ch++) {
        const int b = ch & 1;
        if (ch < NCH - 1) CPA_WAIT1(); else CPA_WAIT0();
        __syncthreads();                       // chunk ch resident for all threads

        const float* ebase = sEDf + b * 8192 + cg * 8;
        const ull*   zb0   = zT + rg;
        ull acc[4][8];
        #pragma unroll
        for (int j = 0; j < 4; j++)
            #pragma unroll
            for (int c = 0; c < 8; c++) acc[j][c] = 0ull;

        // per k: 4 z-LDS.64 (conflict-free) + 2 e-LDS.128 + 8 packs + 32 FFMA2
        #pragma unroll 8
        for (int k = 0; k < CDIM; k++) {
            const ull*    zk = zb0 + k * 64;
            const float4* ek = (const float4*)(ebase + k * 128);
            ull zr_[4] = { zk[0], zk[16], zk[32], zk[48] };   // pairs rg*4+j
            float4 ea = ek[0], eb = ek[1];
            ull er_[8] = { pk2(ea.x, ea.x), pk2(ea.y, ea.y),
                           pk2(ea.z, ea.z), pk2(ea.w, ea.w),
                           pk2(eb.x, eb.x), pk2(eb.y, eb.y),
                           pk2(eb.z, eb.z), pk2(eb.w, eb.w) };
            #pragma unroll
            for (int j = 0; j < 4; j++)
                #pragma unroll
                for (int c = 0; c < 8; c++)
                    acc[j][c] = ffma2(zr_[j], er_[c], acc[j][c]);
        }
        __syncthreads();                       // all threads done with buffer b

        if (ch + 2 < NCH) {                    // refill buffer b with chunk ch+2
            #pragma unroll
            for (int i = 0; i < 8; i++) {
                int u = i * TPB + tid;
                int k = u >> 5, c4 = u & 31;
                cpa16(&sEDf[b * 8192 + k * 128 + c4 * 4],
                      &g_eT[k * NE + (ch + 2) * CH + c4 * 4]);
            }
            CPA_COMMIT();
        }

        // dist = (||z||^2 + ||e||^2) - 2*dot ; strict < + ascending index
        #pragma unroll
        for (int c = 0; c < 8; c++) {
            int ci   = ch * CH + cg * 8 + c;
            float e2 = sE2f[ci];
            ull  e2d = pk2(e2, e2);
            #pragma unroll
            for (int j = 0; j < 4; j++) {
                ull d2 = ffma2(acc[j][c], M2, add2(znj[j], e2d));
                float dlo, dhi; upk2(d2, dlo, dhi);
                if (dlo < best[j * 2])     { best[j * 2]     = dlo; bidx[j * 2]     = ci; }
                if (dhi < best[j * 2 + 1]) { best[j * 2 + 1] = dhi; bidx[j * 2 + 1] = ci; }
            }
        }
    }

    // cross code-group reduction: 16 cgs per row; reuse sEDf
    float* resf = (float*)sEDf;                // [16][128]
    int*   resi = (int*)(sEDf + 2048);         // [16][128]
    __syncthreads();                           // compute done; sEDf reusable
    #pragma unroll
    for (int rl = 0; rl < 8; rl++) {
        int r = rg * 8 + rl;
        resf[cg * 128 + r] = best[rl];
        resi[cg * 128 + r] = bidx[rl];
    }
    __syncthreads();

    if (tid < RPB) {
        float bv = resf[tid]; int bi = resi[tid];
        #pragma unroll
        for (int g = 1; g < 16; g++) {
            float v = resf[g * 128 + tid];
            int  ii = resi[g * 128 + tid];
            if (v < bv || (v == bv && ii < bi)) { bv = v; bi = ii; }
        }
        sidx[tid] = bi;
    }
    __syncthreads();

    // warp-cooperative coalesced output: warp w -> rows w*16..+15
    float ls = 0.f;
    #pragma unroll
    for (int r16 = 0; r16 < 16; r16++) {
        const int row = w * 16 + r16;
        const int code = sidx[row];
        float2 e = ((const float2*)(embs + (size_t)code * CDIM))[ln];
        float2 z = ((const float2*)(ze + (row0 + row) * CDIM))[ln];
        ((float2*)(out + (row0 + row) * CDIM))[ln] = e;
        float d0 = e.x - z.x, d1 = e.y - z.y;
        ls += d0 * d0 + d1 * d1;
    }
    #pragma unroll
    for (int off = 16; off > 0; off >>= 1)
        ls += __shfl_down_sync(0xffffffffu, ls, off);
    if (ln == 0) sred[w] = ls;
    __syncthreads();
    if (tid == 0) {
        float s = 0.f;
        #pragma unroll
        for (int i = 0; i < 8; i++) s += sred[i];
        atomicAdd(&g_loss_acc, (double)s);
    }
}

__global__ void vq_fin(float* loss_out) {
    *loss_out = (float)(1.25 * g_loss_acc / (double)((long long)NROWS * CDIM));
}

extern "C" void kernel_launch(void* const* d_in, const int* in_sizes, int n_in,
                              void* d_out, int out_size) {
    const float* ze   = (const float*)d_in[0];
    const float* embs = (const float*)d_in[1];
    float* out = (float*)d_out;

    cudaFuncSetAttribute(vq_main, cudaFuncAttributeMaxDynamicSharedMemorySize, SMEM_B);

    vq_zero<<<1, 1>>>();                       // launch #1 (profiler shim + init)
    vq_prep<<<NE * CDIM / 256, 256>>>(embs);   // launch #2
    vq_prep2<<<NE / 128, 128>>>(embs);         // launch #3
    vq_main<<<NBLK, TPB, SMEM_B>>>(ze, embs, out);  // launch #4 <- ncu capture
    if (out_size > NROWS * CDIM)
        vq_fin<<<1, 1>>>(out + (out_size - 1));
}